// round 2
// baseline (speedup 1.0000x reference)
#include <cuda_runtime.h>

#define BB 8
#define NN 16384
#define DD 512
#define MV 8
#define NB 64                       // blocks per batch in pass 1/3 (NN/256)
#define SCALE_F 0.1f
#define EPS_F 1e-5f

// Scratch (no cudaMalloc allowed)
__device__ float g_partial[BB][NB][DD];   // 1 MB  column partial sums
__device__ float g_P[BB][NN][MV];         // 4 MB  particle multivectors (dots + bp)
__device__ float g_SW2[BB][MV][DD];       // 128 KB (SCALE * Cayley-folded Wo)
__device__ float g_F[BB][DD];             // 16 KB (SCALE * bo)

// ---------------------------------------------------------------------------
// Pass 1: stream x once. Per row: 8 dot-products -> g_P, plus column partial
// sums -> g_partial. grid (NB, BB), 256 threads (8 warps), 1 row/warp-iter.
// Lane d-slice: d = c*128 + l*4 + j (coalesced LDG.128, conflict-free LDS).
// ---------------------------------------------------------------------------
__global__ void __launch_bounds__(256, 4)
k_pass1(const float* __restrict__ x, const float* __restrict__ Wp,
        const float* __restrict__ bp) {
    __shared__ float Wp_s[MV * DD];          // 16 KB
    __shared__ float bp_s[MV];
    __shared__ float4 col_s[8][DD / 4];      // 16 KB

    int b = blockIdx.y, t = threadIdx.x;
    for (int i = t; i < MV * DD; i += 256) Wp_s[i] = Wp[i];
    if (t < MV) bp_s[t] = bp[t];
    __syncthreads();

    int w = t >> 5, l = t & 31;
    size_t rowbase = (size_t)blockIdx.x * 256 + (size_t)w * 32;
    const float4* xp = (const float4*)(x + ((size_t)b * NN + rowbase) * DD);
    float* Pp = &g_P[b][rowbase][0];

    float4 acc[4];
#pragma unroll
    for (int c = 0; c < 4; ++c) acc[c] = make_float4(0.f, 0.f, 0.f, 0.f);

    int g = l & 7;

    for (int it = 0; it < 32; ++it) {
        float4 v[4];
#pragma unroll
        for (int c = 0; c < 4; ++c) v[c] = xp[(size_t)it * 128 + c * 32 + l];

        // column accumulation for the mean field
#pragma unroll
        for (int c = 0; c < 4; ++c) {
            acc[c].x += v[c].x; acc[c].y += v[c].y;
            acc[c].z += v[c].z; acc[c].w += v[c].w;
        }

        // 8 per-lane partial dots over this lane's 16 d's
        float p[8];
#pragma unroll
        for (int i = 0; i < MV; ++i) {
            float s = 0.f;
#pragma unroll
            for (int c = 0; c < 4; ++c) {
                float4 wv = *(const float4*)&Wp_s[i * DD + c * 128 + l * 4];
                s += v[c].x * wv.x + v[c].y * wv.y + v[c].z * wv.z + v[c].w * wv.w;
            }
            p[i] = s;
        }
        // reduce within 8-lane groups (offsets 1,2,4)
#pragma unroll
        for (int o = 1; o <= 4; o <<= 1) {
#pragma unroll
            for (int i = 0; i < MV; ++i)
                p[i] += __shfl_xor_sync(0xffffffffu, p[i], o);
        }
        // lane picks value (l&7), then reduce across the 4 groups
        float vd = p[0];
#pragma unroll
        for (int i = 1; i < MV; ++i) { if (g == i) vd = p[i]; }
        vd += __shfl_xor_sync(0xffffffffu, vd, 8);
        vd += __shfl_xor_sync(0xffffffffu, vd, 16);
        vd += bp_s[g];
        if (l < MV) Pp[(size_t)it * MV + l] = vd;
    }

    // block-level column reduction: 8 warps -> one 512-float block partial
#pragma unroll
    for (int c = 0; c < 4; ++c) col_s[w][c * 32 + l] = acc[c];
    __syncthreads();
    if (t < 128) {
        float4 s = col_s[0][t];
#pragma unroll
        for (int ww = 1; ww < 8; ++ww) {
            float4 a = col_s[ww][t];
            s.x += a.x; s.y += a.y; s.z += a.z; s.w += a.w;
        }
        ((float4*)&g_partial[b][blockIdx.x][0])[t] = s;
    }
}

// ---------------------------------------------------------------------------
// Pass 2: per-batch prep. One block per batch, 512 threads.
// mean -> meanfield_mv -> Cayley-fold M -> SW2 = SCALE*(M @ Wo^T), F = SCALE*bo
// ---------------------------------------------------------------------------
__global__ void k_prep(const float* __restrict__ Wm, const float* __restrict__ bm,
                       const float* __restrict__ Wo, const float* __restrict__ bo) {
    __shared__ float mean_s[DD];
    __shared__ float mf_s[MV];
    __shared__ float M_s[MV][MV];
    int b = blockIdx.x, t = threadIdx.x;  // 512 threads

    float acc = 0.f;
    for (int s = 0; s < NB; ++s) acc += g_partial[b][s][t];
    mean_s[t] = acc * (1.0f / NN);
    __syncthreads();

    int w = t >> 5, l = t & 31;
    if (w < MV) {
        float p = 0.f;
#pragma unroll
        for (int c = 0; c < 16; ++c) p += mean_s[l + 32 * c] * Wm[w * DD + l + 32 * c];
#pragma unroll
        for (int o = 16; o; o >>= 1) p += __shfl_xor_sync(0xffffffffu, p, o);
        if (l == 0) mf_s[w] = p + bm[w];
    }
    __syncthreads();

    if (t < 64) {
        // Cl(3,0) Cayley: masks in basis order 1,e1,e2,e3,e12,e13,e23,e123
        const int maskT[8] = {0, 1, 2, 4, 3, 5, 6, 7};
        const int idxT[8]  = {0, 1, 2, 4, 3, 5, 6, 7};
        int i = t >> 3, j = t & 7;
        int a = maskT[i], bj = maskT[j];
        int sgn = 0, aa = a >> 1;
        while (aa) { sgn += __popc(aa & bj); aa >>= 1; }
        int k = idxT[a ^ bj];
        M_s[i][k] = ((sgn & 1) ? -1.f : 1.f) * mf_s[j];
    }
    __syncthreads();

    float wo[8];
#pragma unroll
    for (int k = 0; k < 8; ++k) wo[k] = Wo[t * 8 + k];
#pragma unroll
    for (int i = 0; i < MV; ++i) {
        float w2 = 0.f;
#pragma unroll
        for (int k = 0; k < 8; ++k) w2 += M_s[i][k] * wo[k];
        g_SW2[b][i][t] = SCALE_F * w2;
    }
    g_F[b][t] = SCALE_F * bo[t];
}

// ---------------------------------------------------------------------------
// Pass 3: pure streaming. y = LN(x + F + P @ SW2). grid (NB, BB), 256 threads,
// 1 row per warp-iteration, 32 iterations.
// ---------------------------------------------------------------------------
__global__ void __launch_bounds__(256, 4)
k_main(const float* __restrict__ x, const float* __restrict__ gamma,
       const float* __restrict__ beta, float* __restrict__ y) {
    __shared__ float SW2_s[MV * DD];         // 16 KB
    __shared__ float F_s[DD], gm_s[DD], bt_s[DD];

    int b = blockIdx.y, t = threadIdx.x;
    const float* sw2g = &g_SW2[b][0][0];
    for (int i = t; i < MV * DD; i += 256) SW2_s[i] = sw2g[i];
    for (int i = t; i < DD; i += 256) { F_s[i] = g_F[b][i]; gm_s[i] = gamma[i]; bt_s[i] = beta[i]; }
    __syncthreads();

    int w = t >> 5, l = t & 31;
    size_t rowbase = (size_t)blockIdx.x * 256 + (size_t)w * 32;
    const float4* xp = (const float4*)(x + ((size_t)b * NN + rowbase) * DD);
    float4* yp = (float4*)(y + ((size_t)b * NN + rowbase) * DD);
    const float4* Pp = (const float4*)&g_P[b][rowbase][0];

    for (int it = 0; it < 32; ++it) {
        // per-row multivector (uniform across warp -> broadcast loads)
        float4 P0 = __ldg(Pp + (size_t)it * 2);
        float4 P1 = __ldg(Pp + (size_t)it * 2 + 1);

        float4 v[4];
#pragma unroll
        for (int c = 0; c < 4; ++c) v[c] = xp[(size_t)it * 128 + c * 32 + l];

        // v = x + F + sum_i p[i]*SW2[i][:]
#pragma unroll
        for (int c = 0; c < 4; ++c) {
            float4 f4 = *(const float4*)&F_s[c * 128 + l * 4];
            v[c].x += f4.x; v[c].y += f4.y; v[c].z += f4.z; v[c].w += f4.w;
        }
        float pr[8] = {P0.x, P0.y, P0.z, P0.w, P1.x, P1.y, P1.z, P1.w};
#pragma unroll
        for (int i = 0; i < MV; ++i) {
            float pi = pr[i];
#pragma unroll
            for (int c = 0; c < 4; ++c) {
                float4 s4 = *(const float4*)&SW2_s[i * DD + c * 128 + l * 4];
                v[c].x += pi * s4.x; v[c].y += pi * s4.y;
                v[c].z += pi * s4.z; v[c].w += pi * s4.w;
            }
        }

        // LayerNorm (biased var)
        float s = 0.f, q = 0.f;
#pragma unroll
        for (int c = 0; c < 4; ++c) {
            s += v[c].x + v[c].y + v[c].z + v[c].w;
            q += v[c].x * v[c].x + v[c].y * v[c].y + v[c].z * v[c].z + v[c].w * v[c].w;
        }
#pragma unroll
        for (int o = 16; o; o >>= 1) {
            s += __shfl_xor_sync(0xffffffffu, s, o);
            q += __shfl_xor_sync(0xffffffffu, q, o);
        }
        float mu = s * (1.f / DD);
        float r = rsqrtf(q * (1.f / DD) - mu * mu + EPS_F);

#pragma unroll
        for (int c = 0; c < 4; ++c) {
            float4 g4 = *(const float4*)&gm_s[c * 128 + l * 4];
            float4 b4 = *(const float4*)&bt_s[c * 128 + l * 4];
            float4 o4;
            o4.x = g4.x * (v[c].x - mu) * r + b4.x;
            o4.y = g4.y * (v[c].y - mu) * r + b4.y;
            o4.z = g4.z * (v[c].z - mu) * r + b4.z;
            o4.w = g4.w * (v[c].w - mu) * r + b4.w;
            yp[(size_t)it * 128 + c * 32 + l] = o4;
        }
    }
}

// ---------------------------------------------------------------------------
extern "C" void kernel_launch(void* const* d_in, const int* in_sizes, int n_in,
                              void* d_out, int out_size) {
    const float* x     = (const float*)d_in[0];
    const float* Wp    = (const float*)d_in[1];
    const float* bp    = (const float*)d_in[2];
    const float* Wm    = (const float*)d_in[3];
    const float* bm    = (const float*)d_in[4];
    const float* Wo    = (const float*)d_in[5];
    const float* bo    = (const float*)d_in[6];
    const float* gamma = (const float*)d_in[7];
    const float* beta  = (const float*)d_in[8];
    float* y = (float*)d_out;

    dim3 g(NB, BB);
    k_pass1<<<g, 256>>>(x, Wp, bp);
    k_prep<<<BB, 512>>>(Wm, bm, Wo, bo);
    k_main<<<g, 256>>>(x, gamma, beta, y);
}

// round 3
// speedup vs baseline: 1.0525x; 1.0525x over previous
#include <cuda_runtime.h>

#define BB 8
#define NN 16384
#define DD 512
#define MV 8
#define NB 64                       // blocks per batch (NN/256)
#define SCALE_F 0.1f
#define EPS_F 1e-5f

__device__ float g_partial[BB][NB][DD];   // 1 MB  column partial sums
__device__ float g_P[BB][NN][MV];         // 4 MB  particle multivectors (dots + bp)
__device__ float g_SW2[BB][MV][DD];       // 128 KB (SCALE * Cayley-folded Wo)
__device__ float g_F[BB][DD];             // 16 KB (SCALE * bo)

// ---------------------------------------------------------------------------
// Pass 1: stream x once: per-row 8 dots -> g_P, column sums -> g_partial.
// grid (NB, BB), 256 threads. Each warp: 32 rows, 2 rows per iteration
// (Wp shared reads amortized over 2 rows).
// ---------------------------------------------------------------------------
__global__ void __launch_bounds__(256, 3)
k_pass1(const float* __restrict__ x, const float* __restrict__ Wp,
        const float* __restrict__ bp) {
    __shared__ float Wp_s[MV * DD];          // 16 KB
    __shared__ float bp_s[MV];
    __shared__ float4 col_s[8][DD / 4];      // 16 KB

    int b = blockIdx.y, t = threadIdx.x;
    for (int i = t; i < MV * DD; i += 256) Wp_s[i] = Wp[i];
    if (t < MV) bp_s[t] = bp[t];
    __syncthreads();

    int w = t >> 5, l = t & 31;
    size_t rowbase = (size_t)blockIdx.x * 256 + (size_t)w * 32;
    const float4* xp = (const float4*)(x + ((size_t)b * NN + rowbase) * DD);

    float4 acc[4];
#pragma unroll
    for (int c = 0; c < 4; ++c) acc[c] = make_float4(0.f, 0.f, 0.f, 0.f);

    int g = l & 7;

    for (int it = 0; it < 16; ++it) {
        float4 v0[4], v1[4];
#pragma unroll
        for (int c = 0; c < 4; ++c) {
            v0[c] = xp[(size_t)(it * 2) * 128 + c * 32 + l];
            v1[c] = xp[(size_t)(it * 2 + 1) * 128 + c * 32 + l];
        }

        // column accumulation (mean field)
#pragma unroll
        for (int c = 0; c < 4; ++c) {
            acc[c].x += v0[c].x + v1[c].x; acc[c].y += v0[c].y + v1[c].y;
            acc[c].z += v0[c].z + v1[c].z; acc[c].w += v0[c].w + v1[c].w;
        }

        // 8 partial dots per row; Wp LDS shared by both rows
        float p0[8], p1[8];
#pragma unroll
        for (int i = 0; i < MV; ++i) {
            float s0 = 0.f, s1 = 0.f;
#pragma unroll
            for (int c = 0; c < 4; ++c) {
                float4 wv = *(const float4*)&Wp_s[i * DD + c * 128 + l * 4];
                s0 += v0[c].x * wv.x + v0[c].y * wv.y + v0[c].z * wv.z + v0[c].w * wv.w;
                s1 += v1[c].x * wv.x + v1[c].y * wv.y + v1[c].z * wv.z + v1[c].w * wv.w;
            }
            p0[i] = s0; p1[i] = s1;
        }
        // reduce within 8-lane groups (offsets 1,2,4), 16 values in flight
#pragma unroll
        for (int o = 1; o <= 4; o <<= 1) {
#pragma unroll
            for (int i = 0; i < MV; ++i) {
                p0[i] += __shfl_xor_sync(0xffffffffu, p0[i], o);
                p1[i] += __shfl_xor_sync(0xffffffffu, p1[i], o);
            }
        }
        // lane picks component (l&7), combine the four 8-lane groups
        float vd0 = p0[0], vd1 = p1[0];
#pragma unroll
        for (int i = 1; i < MV; ++i) {
            if (g == i) { vd0 = p0[i]; vd1 = p1[i]; }
        }
        vd0 += __shfl_xor_sync(0xffffffffu, vd0, 8);
        vd0 += __shfl_xor_sync(0xffffffffu, vd0, 16);
        vd1 += __shfl_xor_sync(0xffffffffu, vd1, 8);
        vd1 += __shfl_xor_sync(0xffffffffu, vd1, 16);

        if (l < 16) {
            float out = ((l < 8) ? vd0 : vd1) + bp_s[g];
            g_P[b][rowbase + it * 2 + (l >> 3)][g] = out;
        }
    }

    // block-level column reduction
#pragma unroll
    for (int c = 0; c < 4; ++c) col_s[w][c * 32 + l] = acc[c];
    __syncthreads();
    if (t < 128) {
        float4 s = col_s[0][t];
#pragma unroll
        for (int ww = 1; ww < 8; ++ww) {
            float4 a = col_s[ww][t];
            s.x += a.x; s.y += a.y; s.z += a.z; s.w += a.w;
        }
        ((float4*)&g_partial[b][blockIdx.x][0])[t] = s;
    }
}

// ---------------------------------------------------------------------------
// Pass 2: per-batch prep (tiny).
// ---------------------------------------------------------------------------
__global__ void k_prep(const float* __restrict__ Wm, const float* __restrict__ bm,
                       const float* __restrict__ Wo, const float* __restrict__ bo) {
    __shared__ float mean_s[DD];
    __shared__ float mf_s[MV];
    __shared__ float M_s[MV][MV];
    int b = blockIdx.x, t = threadIdx.x;  // 512 threads

    float acc = 0.f;
    for (int s = 0; s < NB; ++s) acc += g_partial[b][s][t];
    mean_s[t] = acc * (1.0f / NN);
    __syncthreads();

    int w = t >> 5, l = t & 31;
    if (w < MV) {
        float p = 0.f;
#pragma unroll
        for (int c = 0; c < 16; ++c) p += mean_s[l + 32 * c] * Wm[w * DD + l + 32 * c];
#pragma unroll
        for (int o = 16; o; o >>= 1) p += __shfl_xor_sync(0xffffffffu, p, o);
        if (l == 0) mf_s[w] = p + bm[w];
    }
    __syncthreads();

    if (t < 64) {
        const int maskT[8] = {0, 1, 2, 4, 3, 5, 6, 7};
        const int idxT[8]  = {0, 1, 2, 4, 3, 5, 6, 7};
        int i = t >> 3, j = t & 7;
        int a = maskT[i], bj = maskT[j];
        int sgn = 0, aa = a >> 1;
        while (aa) { sgn += __popc(aa & bj); aa >>= 1; }
        int k = idxT[a ^ bj];
        M_s[i][k] = ((sgn & 1) ? -1.f : 1.f) * mf_s[j];
    }
    __syncthreads();

    float wo[8];
#pragma unroll
    for (int k = 0; k < 8; ++k) wo[k] = Wo[t * 8 + k];
#pragma unroll
    for (int i = 0; i < MV; ++i) {
        float w2 = 0.f;
#pragma unroll
        for (int k = 0; k < 8; ++k) w2 += M_s[i][k] * wo[k];
        g_SW2[b][i][t] = SCALE_F * w2;
    }
    g_F[b][t] = SCALE_F * bo[t];
}

// ---------------------------------------------------------------------------
// Pass 3: streaming y = LN(x + F + P @ SW2). 2 rows per warp-iteration
// (SW2/F/gamma/beta shared reads amortized over 2 rows).
// ---------------------------------------------------------------------------
__global__ void __launch_bounds__(256, 3)
k_main(const float* __restrict__ x, const float* __restrict__ gamma,
       const float* __restrict__ beta, float* __restrict__ y) {
    __shared__ float SW2_s[MV * DD];         // 16 KB
    __shared__ float F_s[DD], gm_s[DD], bt_s[DD];

    int b = blockIdx.y, t = threadIdx.x;
    const float* sw2g = &g_SW2[b][0][0];
    for (int i = t; i < MV * DD; i += 256) SW2_s[i] = sw2g[i];
    for (int i = t; i < DD; i += 256) { F_s[i] = g_F[b][i]; gm_s[i] = gamma[i]; bt_s[i] = beta[i]; }
    __syncthreads();

    int w = t >> 5, l = t & 31;
    size_t rowbase = (size_t)blockIdx.x * 256 + (size_t)w * 32;
    const float4* xp = (const float4*)(x + ((size_t)b * NN + rowbase) * DD);
    float4* yp = (float4*)(y + ((size_t)b * NN + rowbase) * DD);
    const float4* Pp = (const float4*)&g_P[b][rowbase][0];

    for (int it = 0; it < 16; ++it) {
        float4 P0a = __ldg(Pp + (size_t)it * 4 + 0);
        float4 P0b = __ldg(Pp + (size_t)it * 4 + 1);
        float4 P1a = __ldg(Pp + (size_t)it * 4 + 2);
        float4 P1b = __ldg(Pp + (size_t)it * 4 + 3);

        float4 v0[4], v1[4];
#pragma unroll
        for (int c = 0; c < 4; ++c) {
            v0[c] = xp[(size_t)(it * 2) * 128 + c * 32 + l];
            v1[c] = xp[(size_t)(it * 2 + 1) * 128 + c * 32 + l];
        }

#pragma unroll
        for (int c = 0; c < 4; ++c) {
            float4 f4 = *(const float4*)&F_s[c * 128 + l * 4];
            v0[c].x += f4.x; v0[c].y += f4.y; v0[c].z += f4.z; v0[c].w += f4.w;
            v1[c].x += f4.x; v1[c].y += f4.y; v1[c].z += f4.z; v1[c].w += f4.w;
        }
        float pr0[8] = {P0a.x, P0a.y, P0a.z, P0a.w, P0b.x, P0b.y, P0b.z, P0b.w};
        float pr1[8] = {P1a.x, P1a.y, P1a.z, P1a.w, P1b.x, P1b.y, P1b.z, P1b.w};
#pragma unroll
        for (int i = 0; i < MV; ++i) {
            float a = pr0[i], bq = pr1[i];
#pragma unroll
            for (int c = 0; c < 4; ++c) {
                float4 s4 = *(const float4*)&SW2_s[i * DD + c * 128 + l * 4];
                v0[c].x += a * s4.x;  v0[c].y += a * s4.y;
                v0[c].z += a * s4.z;  v0[c].w += a * s4.w;
                v1[c].x += bq * s4.x; v1[c].y += bq * s4.y;
                v1[c].z += bq * s4.z; v1[c].w += bq * s4.w;
            }
        }

        // LayerNorm stats for both rows
        float s0 = 0.f, q0 = 0.f, s1 = 0.f, q1 = 0.f;
#pragma unroll
        for (int c = 0; c < 4; ++c) {
            s0 += v0[c].x + v0[c].y + v0[c].z + v0[c].w;
            q0 += v0[c].x * v0[c].x + v0[c].y * v0[c].y + v0[c].z * v0[c].z + v0[c].w * v0[c].w;
            s1 += v1[c].x + v1[c].y + v1[c].z + v1[c].w;
            q1 += v1[c].x * v1[c].x + v1[c].y * v1[c].y + v1[c].z * v1[c].z + v1[c].w * v1[c].w;
        }
#pragma unroll
        for (int o = 16; o; o >>= 1) {
            s0 += __shfl_xor_sync(0xffffffffu, s0, o);
            q0 += __shfl_xor_sync(0xffffffffu, q0, o);
            s1 += __shfl_xor_sync(0xffffffffu, s1, o);
            q1 += __shfl_xor_sync(0xffffffffu, q1, o);
        }
        float mu0 = s0 * (1.f / DD), mu1 = s1 * (1.f / DD);
        float r0 = rsqrtf(q0 * (1.f / DD) - mu0 * mu0 + EPS_F);
        float r1 = rsqrtf(q1 * (1.f / DD) - mu1 * mu1 + EPS_F);

#pragma unroll
        for (int c = 0; c < 4; ++c) {
            float4 g4 = *(const float4*)&gm_s[c * 128 + l * 4];
            float4 b4 = *(const float4*)&bt_s[c * 128 + l * 4];
            float4 o0, o1;
            o0.x = g4.x * (v0[c].x - mu0) * r0 + b4.x;
            o0.y = g4.y * (v0[c].y - mu0) * r0 + b4.y;
            o0.z = g4.z * (v0[c].z - mu0) * r0 + b4.z;
            o0.w = g4.w * (v0[c].w - mu0) * r0 + b4.w;
            o1.x = g4.x * (v1[c].x - mu1) * r1 + b4.x;
            o1.y = g4.y * (v1[c].y - mu1) * r1 + b4.y;
            o1.z = g4.z * (v1[c].z - mu1) * r1 + b4.z;
            o1.w = g4.w * (v1[c].w - mu1) * r1 + b4.w;
            yp[(size_t)(it * 2) * 128 + c * 32 + l] = o0;
            yp[(size_t)(it * 2 + 1) * 128 + c * 32 + l] = o1;
        }
    }
}

// ---------------------------------------------------------------------------
extern "C" void kernel_launch(void* const* d_in, const int* in_sizes, int n_in,
                              void* d_out, int out_size) {
    const float* x     = (const float*)d_in[0];
    const float* Wp    = (const float*)d_in[1];
    const float* bp    = (const float*)d_in[2];
    const float* Wm    = (const float*)d_in[3];
    const float* bm    = (const float*)d_in[4];
    const float* Wo    = (const float*)d_in[5];
    const float* bo    = (const float*)d_in[6];
    const float* gamma = (const float*)d_in[7];
    const float* beta  = (const float*)d_in[8];
    float* y = (float*)d_out;

    dim3 g(NB, BB);
    k_pass1<<<g, 256>>>(x, Wp, bp);
    k_prep<<<BB, 512>>>(Wm, bm, Wo, bo);
    k_main<<<g, 256>>>(x, gamma, beta, y);
}

// round 4
// speedup vs baseline: 1.5639x; 1.4859x over previous
#include <cuda_runtime.h>
#include <cuda_bf16.h>

#define BB 8
#define NN 16384
#define DD 512
#define MV 8
#define SS 128                      // N-splits in pass 1
#define RPS (NN / SS)               // rows per split = 128
#define NBLK 128                    // blocks per batch in pass 3 (128 rows each)
#define SCALE_F 0.1f
#define EPS_F 1e-5f

__device__ float g_partial[BB][SS][DD];        // 2 MB  column partial sums
__device__ float g_F[BB][DD];                  // F' = SCALE*(bo + sum_i bp_i*W2_i)
__device__ __nv_bfloat16 g_Wph[MV * DD];       // Wp in bf16
__device__ __nv_bfloat16 g_SW2h[BB][MV * DD];  // SCALE*Cayley-folded Wo, bf16

// ---------------------------------------------------------------------------
// Pass 1: pure streaming column sums (proven 44us @ 78% DRAM).
// grid (SS, BB), 128 threads.
// ---------------------------------------------------------------------------
__global__ void k_partial(const float* __restrict__ x) {
    int b = blockIdx.y, s = blockIdx.x, t = threadIdx.x;  // t in [0,128)
    const float4* xp = (const float4*)(x + ((size_t)b * NN + (size_t)s * RPS) * DD);
    float4 a0 = make_float4(0.f, 0.f, 0.f, 0.f);
    float4 a1 = make_float4(0.f, 0.f, 0.f, 0.f);
#pragma unroll 4
    for (int r = 0; r < RPS; r += 2) {
        float4 v0 = xp[(size_t)r * 128 + t];
        float4 v1 = xp[(size_t)(r + 1) * 128 + t];
        a0.x += v0.x; a0.y += v0.y; a0.z += v0.z; a0.w += v0.w;
        a1.x += v1.x; a1.y += v1.y; a1.z += v1.z; a1.w += v1.w;
    }
    a0.x += a1.x; a0.y += a1.y; a0.z += a1.z; a0.w += a1.w;
    ((float4*)&g_partial[b][s][0])[t] = a0;
}

// ---------------------------------------------------------------------------
// Pass 2: per-batch prep. mean -> mf -> Cayley fold -> SW2(bf16), F', Wp(bf16)
// ---------------------------------------------------------------------------
__global__ void k_prep(const float* __restrict__ Wm, const float* __restrict__ bm,
                       const float* __restrict__ Wo, const float* __restrict__ bp,
                       const float* __restrict__ bo, const float* __restrict__ Wp) {
    __shared__ float mean_s[DD];
    __shared__ float mf_s[MV];
    __shared__ float M_s[MV][MV];
    int b = blockIdx.x, t = threadIdx.x;  // 512 threads

    float acc = 0.f;
    for (int s = 0; s < SS; ++s) acc += g_partial[b][s][t];
    mean_s[t] = acc * (1.0f / NN);

    // bf16 copy of Wp (all blocks write identical values - deterministic)
#pragma unroll
    for (int i = 0; i < MV; ++i)
        g_Wph[i * DD + t] = __float2bfloat16(Wp[i * DD + t]);
    __syncthreads();

    int w = t >> 5, l = t & 31;
    if (w < MV) {
        float p = 0.f;
#pragma unroll
        for (int c = 0; c < 16; ++c) p += mean_s[l + 32 * c] * Wm[w * DD + l + 32 * c];
#pragma unroll
        for (int o = 16; o; o >>= 1) p += __shfl_xor_sync(0xffffffffu, p, o);
        if (l == 0) mf_s[w] = p + bm[w];
    }
    __syncthreads();

    if (t < 64) {
        const int maskT[8] = {0, 1, 2, 4, 3, 5, 6, 7};
        const int idxT[8]  = {0, 1, 2, 4, 3, 5, 6, 7};
        int i = t >> 3, j = t & 7;
        int a = maskT[i], bj = maskT[j];
        int sgn = 0, aa = a >> 1;
        while (aa) { sgn += __popc(aa & bj); aa >>= 1; }
        int k = idxT[a ^ bj];
        M_s[i][k] = ((sgn & 1) ? -1.f : 1.f) * mf_s[j];
    }
    __syncthreads();

    float wo[8];
#pragma unroll
    for (int k = 0; k < 8; ++k) wo[k] = Wo[t * 8 + k];
    float fb = 0.f;
#pragma unroll
    for (int i = 0; i < MV; ++i) {
        float w2 = 0.f;
#pragma unroll
        for (int k = 0; k < 8; ++k) w2 += M_s[i][k] * wo[k];
        g_SW2h[b][i * DD + t] = __float2bfloat16(SCALE_F * w2);
        fb += bp[i] * w2;
    }
    g_F[b][t] = SCALE_F * (fb + bo[t]);
}

// ---------------------------------------------------------------------------
// Pass 3: fused dots + combine + LN. grid (NBLK, BB), 256 threads, 8 warps.
// Warp processes 16 rows, 2 per iteration. Weights bf16 in shared.
// ---------------------------------------------------------------------------
__global__ void __launch_bounds__(256, 3)
k_main(const float* __restrict__ x, const float* __restrict__ gamma,
       const float* __restrict__ beta, float* __restrict__ y) {
    __shared__ __nv_bfloat16 Wp_s[MV * DD];    // 8 KB
    __shared__ __nv_bfloat16 SW2_s[MV * DD];   // 8 KB
    __shared__ float F_s[DD], gm_s[DD], bt_s[DD];

    int b = blockIdx.y, t = threadIdx.x;
    const __nv_bfloat16* sw2g = &g_SW2h[b][0];
    for (int i = t; i < MV * DD; i += 256) { Wp_s[i] = g_Wph[i]; SW2_s[i] = sw2g[i]; }
    for (int i = t; i < DD; i += 256) { F_s[i] = g_F[b][i]; gm_s[i] = gamma[i]; bt_s[i] = beta[i]; }
    __syncthreads();

    int w = t >> 5, l = t & 31;
    int g = l & 7;
    size_t rowbase = (size_t)blockIdx.x * 128 + (size_t)w * 16;
    const float4* xp = (const float4*)(x + ((size_t)b * NN + rowbase) * DD);
    float4* yp = (float4*)(y + ((size_t)b * NN + rowbase) * DD);

    for (int it = 0; it < 8; ++it) {
        float4 v0[4], v1[4];
#pragma unroll
        for (int c = 0; c < 4; ++c) {
            v0[c] = xp[(size_t)(it * 2) * 128 + c * 32 + l];
            v1[c] = xp[(size_t)(it * 2 + 1) * 128 + c * 32 + l];
        }

        // 8 per-lane partial dots per row (bf16 weights)
        float p0[8], p1[8];
#pragma unroll
        for (int i = 0; i < MV; ++i) {
            float s0 = 0.f, s1 = 0.f;
#pragma unroll
            for (int c = 0; c < 4; ++c) {
                uint2 u = *(const uint2*)&Wp_s[i * DD + c * 128 + l * 4];
                float2 a01 = __bfloat1622float2(*(const __nv_bfloat162*)&u.x);
                float2 a23 = __bfloat1622float2(*(const __nv_bfloat162*)&u.y);
                s0 += v0[c].x * a01.x + v0[c].y * a01.y + v0[c].z * a23.x + v0[c].w * a23.y;
                s1 += v1[c].x * a01.x + v1[c].y * a01.y + v1[c].z * a23.x + v1[c].w * a23.y;
            }
            p0[i] = s0; p1[i] = s1;
        }
        // group reduce (1,2,4), select component g, cross-group (8,16)
#pragma unroll
        for (int o = 1; o <= 4; o <<= 1) {
#pragma unroll
            for (int i = 0; i < MV; ++i) {
                p0[i] += __shfl_xor_sync(0xffffffffu, p0[i], o);
                p1[i] += __shfl_xor_sync(0xffffffffu, p1[i], o);
            }
        }
        float vd0 = p0[0], vd1 = p1[0];
#pragma unroll
        for (int i = 1; i < MV; ++i) { if (g == i) { vd0 = p0[i]; vd1 = p1[i]; } }
        vd0 += __shfl_xor_sync(0xffffffffu, vd0, 8);
        vd0 += __shfl_xor_sync(0xffffffffu, vd0, 16);
        vd1 += __shfl_xor_sync(0xffffffffu, vd1, 8);
        vd1 += __shfl_xor_sync(0xffffffffu, vd1, 16);
        // broadcast: component i lives in lane i (among others)
        float pr0[8], pr1[8];
#pragma unroll
        for (int i = 0; i < MV; ++i) {
            pr0[i] = __shfl_sync(0xffffffffu, vd0, i);
            pr1[i] = __shfl_sync(0xffffffffu, vd1, i);
        }

        // v = x + F' + sum_i P_i * SW2[i][:]
#pragma unroll
        for (int c = 0; c < 4; ++c) {
            float4 f4 = *(const float4*)&F_s[c * 128 + l * 4];
            v0[c].x += f4.x; v0[c].y += f4.y; v0[c].z += f4.z; v0[c].w += f4.w;
            v1[c].x += f4.x; v1[c].y += f4.y; v1[c].z += f4.z; v1[c].w += f4.w;
        }
#pragma unroll
        for (int i = 0; i < MV; ++i) {
            float a = pr0[i], bq = pr1[i];
#pragma unroll
            for (int c = 0; c < 4; ++c) {
                uint2 u = *(const uint2*)&SW2_s[i * DD + c * 128 + l * 4];
                float2 s01 = __bfloat1622float2(*(const __nv_bfloat162*)&u.x);
                float2 s23 = __bfloat1622float2(*(const __nv_bfloat162*)&u.y);
                v0[c].x += a * s01.x;  v0[c].y += a * s01.y;
                v0[c].z += a * s23.x;  v0[c].w += a * s23.y;
                v1[c].x += bq * s01.x; v1[c].y += bq * s01.y;
                v1[c].z += bq * s23.x; v1[c].w += bq * s23.y;
            }
        }

        // LayerNorm stats: {s0,q0,s1,q1} via group reduce + select + cross
        float s0 = 0.f, q0 = 0.f, s1 = 0.f, q1 = 0.f;
#pragma unroll
        for (int c = 0; c < 4; ++c) {
            s0 += v0[c].x + v0[c].y + v0[c].z + v0[c].w;
            q0 += v0[c].x * v0[c].x + v0[c].y * v0[c].y + v0[c].z * v0[c].z + v0[c].w * v0[c].w;
            s1 += v1[c].x + v1[c].y + v1[c].z + v1[c].w;
            q1 += v1[c].x * v1[c].x + v1[c].y * v1[c].y + v1[c].z * v1[c].z + v1[c].w * v1[c].w;
        }
#pragma unroll
        for (int o = 1; o <= 2; o <<= 1) {
            s0 += __shfl_xor_sync(0xffffffffu, s0, o);
            q0 += __shfl_xor_sync(0xffffffffu, q0, o);
            s1 += __shfl_xor_sync(0xffffffffu, s1, o);
            q1 += __shfl_xor_sync(0xffffffffu, q1, o);
        }
        int g4i = l & 3;
        float sel = s0;
        if (g4i == 1) sel = q0;
        if (g4i == 2) sel = s1;
        if (g4i == 3) sel = q1;
        sel += __shfl_xor_sync(0xffffffffu, sel, 4);
        sel += __shfl_xor_sync(0xffffffffu, sel, 8);
        sel += __shfl_xor_sync(0xffffffffu, sel, 16);
        float S0 = __shfl_sync(0xffffffffu, sel, 0);
        float Q0 = __shfl_sync(0xffffffffu, sel, 1);
        float S1 = __shfl_sync(0xffffffffu, sel, 2);
        float Q1 = __shfl_sync(0xffffffffu, sel, 3);

        float mu0 = S0 * (1.f / DD), mu1 = S1 * (1.f / DD);
        float r0 = rsqrtf(Q0 * (1.f / DD) - mu0 * mu0 + EPS_F);
        float r1 = rsqrtf(Q1 * (1.f / DD) - mu1 * mu1 + EPS_F);

#pragma unroll
        for (int c = 0; c < 4; ++c) {
            float4 g4 = *(const float4*)&gm_s[c * 128 + l * 4];
            float4 b4 = *(const float4*)&bt_s[c * 128 + l * 4];
            float4 o0, o1;
            o0.x = g4.x * (v0[c].x - mu0) * r0 + b4.x;
            o0.y = g4.y * (v0[c].y - mu0) * r0 + b4.y;
            o0.z = g4.z * (v0[c].z - mu0) * r0 + b4.z;
            o0.w = g4.w * (v0[c].w - mu0) * r0 + b4.w;
            o1.x = g4.x * (v1[c].x - mu1) * r1 + b4.x;
            o1.y = g4.y * (v1[c].y - mu1) * r1 + b4.y;
            o1.z = g4.z * (v1[c].z - mu1) * r1 + b4.z;
            o1.w = g4.w * (v1[c].w - mu1) * r1 + b4.w;
            yp[(size_t)(it * 2) * 128 + c * 32 + l] = o0;
            yp[(size_t)(it * 2 + 1) * 128 + c * 32 + l] = o1;
        }
    }
}

// ---------------------------------------------------------------------------
extern "C" void kernel_launch(void* const* d_in, const int* in_sizes, int n_in,
                              void* d_out, int out_size) {
    const float* x     = (const float*)d_in[0];
    const float* Wp    = (const float*)d_in[1];
    const float* bp    = (const float*)d_in[2];
    const float* Wm    = (const float*)d_in[3];
    const float* bm    = (const float*)d_in[4];
    const float* Wo    = (const float*)d_in[5];
    const float* bo    = (const float*)d_in[6];
    const float* gamma = (const float*)d_in[7];
    const float* beta  = (const float*)d_in[8];
    float* y = (float*)d_out;

    dim3 g1(SS, BB);
    k_partial<<<g1, 128>>>(x);
    k_prep<<<BB, 512>>>(Wm, bm, Wo, bp, bo, Wp);
    dim3 g3(NBLK, BB);
    k_main<<<g3, 256>>>(x, gamma, beta, y);
}